// round 11
// baseline (speedup 1.0000x reference)
#include <cuda_runtime.h>
#include <cuda_fp16.h>
#include <cstdint>
#include <math.h>

#define BDIM 4096
#define DDIM 1024
#define TM 128
#define TN 128
#define NBLK (BDIM / TM)      // 32 row/col blocks
#define NTILES (NBLK * NBLK)  // 1024
#define GRID_P 296            // persistent: 2 CTAs/SM x 148 SMs
#define NS 3                  // cp.async pipeline stages
#define KC 64                 // k-halfs per chunk
#define NCHUNK (DDIM / KC)    // 16
#define ROW_B 128             // bytes per smem row (no padding; XOR swizzle)
#define TILE_B (TM * ROW_B)   // 16384 B per tile
#define STAGE_B (2 * TILE_B)  // A + B per stage = 32768 B
#define SCALE 20.0f

// Scratch (allocation-free per harness rules)
__device__ __half g_a16[BDIM * DDIM];
__device__ __half g_p16[BDIM * DDIM];
__device__ float g_inv_a[BDIM];
__device__ float g_inv_p[BDIM];
__device__ float g_partial[BDIM * NBLK];
__device__ float g_diag[BDIM];
__device__ float g_blocksum[NBLK];
__device__ int g_count;               // zero-init; reset to 0 after each use

// ---------------------------------------------------------------- helpers
__device__ __forceinline__ uint32_t smem_u32(const void* p) {
    uint32_t a;
    asm("{ .reg .u64 t; cvta.to.shared.u64 t, %1; cvt.u32.u64 %0, t; }" : "=r"(a) : "l"(p));
    return a;
}
__device__ __forceinline__ uint32_t h2_bits(__half2 h) {
    return *reinterpret_cast<const uint32_t*>(&h);
}
__device__ __forceinline__ void cp_async16(uint32_t dst, const void* src) {
    asm volatile("cp.async.cg.shared.global [%0], [%1], 16;" :: "r"(dst), "l"(src));
}
#define CP_COMMIT() asm volatile("cp.async.commit_group;" ::: "memory")
template <int N>
__device__ __forceinline__ void cp_wait() {
    asm volatile("cp.async.wait_group %0;" :: "n"(N) : "memory");
}
__device__ __forceinline__ void ldsm_x4(uint32_t* r, uint32_t addr) {
    asm volatile("ldmatrix.sync.aligned.m8n8.x4.shared.b16 {%0,%1,%2,%3}, [%4];"
                 : "=r"(r[0]), "=r"(r[1]), "=r"(r[2]), "=r"(r[3]) : "r"(addr));
}
// fp16 tensor-core MMA, fp32 accumulate: base-target PTX (sm_80+).
__device__ __forceinline__ void mma_f16(float* d, const uint32_t* a, const uint32_t* b) {
    asm volatile(
        "mma.sync.aligned.m16n8k16.row.col.f32.f16.f16.f32 "
        "{%0,%1,%2,%3}, {%4,%5,%6,%7}, {%8,%9}, {%0,%1,%2,%3};"
        : "+f"(d[0]), "+f"(d[1]), "+f"(d[2]), "+f"(d[3])
        : "r"(a[0]), "r"(a[1]), "r"(a[2]), "r"(a[3]), "r"(b[0]), "r"(b[1]));
}

// ---------------------------------------------------------------------------
// 1) Row inverse norms + fp32->fp16 conversion. One warp per TWO rows
//    (interleaved loads -> MLP 16 per thread). grid = 512 x 256.
// ---------------------------------------------------------------------------
__global__ void norm_kernel(const float* __restrict__ A, const float* __restrict__ P) {
    const bool isA  = blockIdx.x < 256;
    const int rbase = (blockIdx.x & 255) * 16 + (threadIdx.x >> 5) * 2;
    const int lane  = threadIdx.x & 31;
    const float* src = isA ? A : P;
    __half* dstm = isA ? g_a16 : g_p16;
    const float4* s0 = (const float4*)(src + (size_t)rbase * DDIM);
    const float4* s1 = (const float4*)(src + (size_t)(rbase + 1) * DDIM);

    float4 v0[8], v1[8];
    #pragma unroll
    for (int i = 0; i < 4; i++) {      // interleave both rows: 16 loads in flight
        v0[2 * i]     = s0[i * 64 + lane * 2];
        v0[2 * i + 1] = s0[i * 64 + lane * 2 + 1];
        v1[2 * i]     = s1[i * 64 + lane * 2];
        v1[2 * i + 1] = s1[i * 64 + lane * 2 + 1];
    }
    float sa = 0.0f, sb = 0.0f;
    #pragma unroll
    for (int i = 0; i < 8; i++) {
        sa += v0[i].x * v0[i].x + v0[i].y * v0[i].y + v0[i].z * v0[i].z + v0[i].w * v0[i].w;
        sb += v1[i].x * v1[i].x + v1[i].y * v1[i].y + v1[i].z * v1[i].z + v1[i].w * v1[i].w;
    }
    uint4* d0 = (uint4*)(dstm + (size_t)rbase * DDIM);
    uint4* d1 = (uint4*)(dstm + (size_t)(rbase + 1) * DDIM);
    #pragma unroll
    for (int i = 0; i < 4; i++) {
        uint4 p0, p1;
        p0.x = h2_bits(__floats2half2_rn(v0[2*i].x,   v0[2*i].y));
        p0.y = h2_bits(__floats2half2_rn(v0[2*i].z,   v0[2*i].w));
        p0.z = h2_bits(__floats2half2_rn(v0[2*i+1].x, v0[2*i+1].y));
        p0.w = h2_bits(__floats2half2_rn(v0[2*i+1].z, v0[2*i+1].w));
        d0[i * 32 + lane] = p0;
        p1.x = h2_bits(__floats2half2_rn(v1[2*i].x,   v1[2*i].y));
        p1.y = h2_bits(__floats2half2_rn(v1[2*i].z,   v1[2*i].w));
        p1.z = h2_bits(__floats2half2_rn(v1[2*i+1].x, v1[2*i+1].y));
        p1.w = h2_bits(__floats2half2_rn(v1[2*i+1].z, v1[2*i+1].w));
        d1[i * 32 + lane] = p1;
    }
    #pragma unroll
    for (int o = 16; o > 0; o >>= 1) {
        sa += __shfl_xor_sync(0xffffffffu, sa, o);
        sb += __shfl_xor_sync(0xffffffffu, sb, o);
    }
    if (lane == 0) {
        float* invm = isA ? g_inv_a : g_inv_p;
        invm[rbase]     = 1.0f / fmaxf(sqrtf(sa), 1e-8f);
        invm[rbase + 1] = 1.0f / fmaxf(sqrtf(sb), 1e-8f);
    }
}

// ---------------------------------------------------------------------------
// 2) Persistent fp16 mma.sync GEMM: 296 CTAs, each loops 3-4 tiles with a
//    chunk pipeline flattened ACROSS tile boundaries (epilogue overlaps the
//    next tile's loads). 128x128 tile, XOR-swizzled smem, NS=3, 2 CTAs/SM.
// ---------------------------------------------------------------------------
__device__ __forceinline__ void load_stream(char* smc, int s, int bid, int tid) {
    const int tt   = bid + (s >> 4) * GRID_P;      // tile index for stream pos s
    const int k0   = (s & 15) * KC;
    const __half* Ab = g_a16 + (size_t)(tt >> 5) * TM * DDIM;
    const __half* Pb = g_p16 + (size_t)(tt & 31) * TN * DDIM;
    char* st = smc + (s % NS) * STAGE_B;
    const int row = tid >> 3, q = tid & 7;
    #pragma unroll
    for (int j = 0; j < 4; j++) {
        int r = j * 32 + row;
        uint32_t dst = smem_u32(st + r * ROW_B + ((q ^ (r & 7)) << 4));
        cp_async16(dst, Ab + (size_t)r * DDIM + k0 + q * 8);
    }
    char* stb = st + TILE_B;
    #pragma unroll
    for (int j = 0; j < 4; j++) {
        int r = j * 32 + row;
        uint32_t dst = smem_u32(stb + r * ROW_B + ((q ^ (r & 7)) << 4));
        cp_async16(dst, Pb + (size_t)r * DDIM + k0 + q * 8);
    }
    CP_COMMIT();
}

__global__ __launch_bounds__(256, 2) void gemm_mma_kernel() {
    extern __shared__ char smc[];
    __shared__ float s_ia[TM];
    __shared__ float s_ip[TN];
    __shared__ float red[TM][2];

    const int tid  = threadIdx.x;
    const int lane = tid & 31;
    const int wid  = tid >> 5;
    const int wm   = (wid & 3) * 32;
    const int wn   = (wid >> 2) * 64;
    const int bid  = blockIdx.x;

    const int nt    = (NTILES - bid + GRID_P - 1) / GRID_P;   // 3 or 4 tiles
    const int total = nt * NCHUNK;

    const int lt = lane >> 3, lr = lane & 7;
    int rowA[2], rowB[4];
    #pragma unroll
    for (int mt = 0; mt < 2; mt++) rowA[mt] = wm + mt * 16 + (lt & 1) * 8 + lr;
    #pragma unroll
    for (int np = 0; np < 4; np++) rowB[np] = wn + np * 16 + (lt >> 1) * 8 + lr;
    const int idxA = lt >> 1;
    const int idxB = lt & 1;

    load_stream(smc, 0, bid, tid);
    load_stream(smc, 1, bid, tid);

    for (int i = 0; i < nt; i++) {
        const int t = bid + i * GRID_P;
        const int brow = t >> 5, bcol = t & 31;

        float acc[2][8][4];
        #pragma unroll
        for (int mt = 0; mt < 2; mt++)
            #pragma unroll
            for (int ntt = 0; ntt < 8; ntt++)
                #pragma unroll
                for (int r = 0; r < 4; r++) acc[mt][ntt][r] = 0.0f;

        for (int c = 0; c < NCHUNK; c++) {
            const int s = i * NCHUNK + c;
            if (s == total - 1) cp_wait<0>(); else cp_wait<1>();
            __syncthreads();                 // publish chunk s; closes WAR + s_ia reuse
            if (c == 0) {                    // stage norms for this tile (read in epilogue)
                if (tid < 128) s_ia[tid]       = SCALE * g_inv_a[brow * TM + tid];
                else           s_ip[tid - 128] = g_inv_p[bcol * TN + (tid - 128)];
            }
            if (s + NS - 1 < total) load_stream(smc, s + NS - 1, bid, tid);

            const char* sA = smc + (s % NS) * STAGE_B;
            const char* sB = sA + TILE_B;

            #pragma unroll
            for (int kk = 0; kk < 4; kk++) {
                uint32_t a[2][4], bf[16];
                #pragma unroll
                for (int mt = 0; mt < 2; mt++) {
                    int slot = (idxA | (kk << 1)) ^ (rowA[mt] & 7);
                    ldsm_x4(a[mt], smem_u32(sA + rowA[mt] * ROW_B + (slot << 4)));
                }
                #pragma unroll
                for (int np = 0; np < 4; np++) {
                    int slot = (idxB | (kk << 1)) ^ (rowB[np] & 7);
                    ldsm_x4(&bf[np * 4], smem_u32(sB + rowB[np] * ROW_B + (slot << 4)));
                }
                #pragma unroll
                for (int mt = 0; mt < 2; mt++)
                    #pragma unroll
                    for (int ntt = 0; ntt < 8; ntt++)
                        mma_f16(acc[mt][ntt], a[mt], &bf[ntt * 2]);
            }
        }
        __syncthreads();   // mainloop done; red[] free from previous tile

        // Epilogue (overlaps next tile's in-flight cp.async loads)
        float rs[2][2] = {{0.0f, 0.0f}, {0.0f, 0.0f}};
        #pragma unroll
        for (int mt = 0; mt < 2; mt++) {
            #pragma unroll
            for (int h = 0; h < 2; h++) {
                const int rloc = wm + mt * 16 + (lane >> 2) + h * 8;
                const float ia = s_ia[rloc];
                const int grow = brow * TM + rloc;
                float acc_rs = 0.0f;
                #pragma unroll
                for (int ntt = 0; ntt < 8; ntt++) {
                    const int cbase = wn + ntt * 8 + (lane & 3) * 2;
                    const float ip0 = s_ip[cbase], ip1 = s_ip[cbase + 1];
                    float s0 = acc[mt][ntt][h * 2 + 0] * ia * ip0;
                    float s1 = acc[mt][ntt][h * 2 + 1] * ia * ip1;
                    acc_rs += __expf(s0 - SCALE) + __expf(s1 - SCALE);
                    if (brow == bcol) {
                        if (rloc == cbase)     g_diag[grow] = s0;
                        if (rloc == cbase + 1) g_diag[grow] = s1;
                    }
                }
                rs[mt][h] = acc_rs;
            }
        }
        #pragma unroll
        for (int mt = 0; mt < 2; mt++)
            #pragma unroll
            for (int h = 0; h < 2; h++) {
                rs[mt][h] += __shfl_xor_sync(0xffffffffu, rs[mt][h], 1);
                rs[mt][h] += __shfl_xor_sync(0xffffffffu, rs[mt][h], 2);
            }
        if ((lane & 3) == 0) {
            #pragma unroll
            for (int mt = 0; mt < 2; mt++)
                #pragma unroll
                for (int h = 0; h < 2; h++)
                    red[wm + mt * 16 + (lane >> 2) + h * 8][wid >> 2] = rs[mt][h];
        }
        __syncthreads();
        if (tid < TM) {
            float v = red[tid][0] + red[tid][1];
            g_partial[(size_t)(brow * TM + tid) * NBLK + bcol] = v;
        }
    }
}

// ---------------------------------------------------------------------------
// 3) Fused tail: per-row loss, per-block sum, last block finalizes (fixed
//    order -> deterministic). g_count reset for graph replays.
// ---------------------------------------------------------------------------
__global__ void rowloss_kernel(float* __restrict__ out) {
    __shared__ float ws[4];
    const int r = blockIdx.x * 128 + threadIdx.x;
    float s = 0.0f;
    #pragma unroll
    for (int c = 0; c < NBLK; c++) s += g_partial[(size_t)r * NBLK + c];
    float rl = logf(s) + SCALE - g_diag[r];
    #pragma unroll
    for (int o = 16; o > 0; o >>= 1) rl += __shfl_xor_sync(0xffffffffu, rl, o);
    if ((threadIdx.x & 31) == 0) ws[threadIdx.x >> 5] = rl;
    __syncthreads();
    if (threadIdx.x == 0) {
        g_blocksum[blockIdx.x] = ws[0] + ws[1] + ws[2] + ws[3];
        __threadfence();
        int v = atomicAdd(&g_count, 1);
        if (v == NBLK - 1) {
            float tt = 0.0f;
            #pragma unroll
            for (int i = 0; i < NBLK; i++) tt += g_blocksum[i];
            out[0] = tt * (1.0f / (float)BDIM);
            g_count = 0;
        }
    }
}

// ---------------------------------------------------------------------------
extern "C" void kernel_launch(void* const* d_in, const int* in_sizes, int n_in,
                              void* d_out, int out_size) {
    const float* A = (const float*)d_in[0];   // anchor_emb  [4096, 1024]
    const float* P = (const float*)d_in[1];   // pos_negs_emb[4096, 1024]
    float* out = (float*)d_out;

    const int smem = NS * STAGE_B;            // 98304 B -> 2 CTAs/SM
    cudaFuncSetAttribute(gemm_mma_kernel,
                         cudaFuncAttributeMaxDynamicSharedMemorySize, smem);

    norm_kernel<<<512, 256>>>(A, P);
    gemm_mma_kernel<<<GRID_P, 256, smem>>>();
    rowloss_kernel<<<NBLK, 128>>>(out);
}

// round 13
// speedup vs baseline: 1.0529x; 1.0529x over previous
#include <cuda_runtime.h>
#include <cuda_fp16.h>
#include <cstdint>
#include <math.h>

#define BDIM 4096
#define DDIM 1024
#define TM 128
#define TN 128
#define NBLK (BDIM / TM)      // 32 row/col blocks
#define NS 3                  // cp.async pipeline stages
#define KC 64                 // k-halfs per chunk
#define NCHUNK (DDIM / KC)    // 16
#define ROW_B 128             // bytes per smem row (no padding; XOR swizzle)
#define TILE_B (TM * ROW_B)   // 16384 B per tile
#define STAGE_B (2 * TILE_B)  // A + B per stage = 32768 B
#define SCALE 20.0f

// Scratch (allocation-free per harness rules)
__device__ __half g_a16[BDIM * DDIM];
__device__ __half g_p16[BDIM * DDIM];
__device__ float g_inv_a[BDIM];
__device__ float g_inv_p[BDIM];
__device__ float g_partial[BDIM * NBLK];
__device__ float g_diag[BDIM];
__device__ float g_blocksum[NBLK];
__device__ int g_count;               // zero-init; reset to 0 after each use

// ---------------------------------------------------------------- helpers
__device__ __forceinline__ uint32_t smem_u32(const void* p) {
    uint32_t a;
    asm("{ .reg .u64 t; cvta.to.shared.u64 t, %1; cvt.u32.u64 %0, t; }" : "=r"(a) : "l"(p));
    return a;
}
__device__ __forceinline__ uint32_t h2_bits(__half2 h) {
    return *reinterpret_cast<const uint32_t*>(&h);
}
__device__ __forceinline__ void cp_async16(uint32_t dst, const void* src) {
    asm volatile("cp.async.cg.shared.global [%0], [%1], 16;" :: "r"(dst), "l"(src));
}
#define CP_COMMIT() asm volatile("cp.async.commit_group;" ::: "memory")
template <int N>
__device__ __forceinline__ void cp_wait() {
    asm volatile("cp.async.wait_group %0;" :: "n"(N) : "memory");
}
__device__ __forceinline__ void ldsm_x4(uint32_t* r, uint32_t addr) {
    asm volatile("ldmatrix.sync.aligned.m8n8.x4.shared.b16 {%0,%1,%2,%3}, [%4];"
                 : "=r"(r[0]), "=r"(r[1]), "=r"(r[2]), "=r"(r[3]) : "r"(addr));
}
// fp16 tensor-core MMA, fp32 accumulate: base-target PTX (sm_80+).
__device__ __forceinline__ void mma_f16(float* d, const uint32_t* a, const uint32_t* b) {
    asm volatile(
        "mma.sync.aligned.m16n8k16.row.col.f32.f16.f16.f32 "
        "{%0,%1,%2,%3}, {%4,%5,%6,%7}, {%8,%9}, {%0,%1,%2,%3};"
        : "+f"(d[0]), "+f"(d[1]), "+f"(d[2]), "+f"(d[3])
        : "r"(a[0]), "r"(a[1]), "r"(a[2]), "r"(a[3]), "r"(b[0]), "r"(b[1]));
}

// ---------------------------------------------------------------------------
// 1) Row inverse norms + fp32->fp16 conversion. One warp per row (R10 shape).
// ---------------------------------------------------------------------------
__global__ void norm_kernel(const float* __restrict__ A, const float* __restrict__ P) {
    const int row  = (blockIdx.x & 511) * 8 + (threadIdx.x >> 5);
    const bool isA = blockIdx.x < 512;
    const int lane = threadIdx.x & 31;
    const float4* src = (const float4*)((isA ? A : P) + (size_t)row * DDIM);
    uint4* dst = (uint4*)((isA ? g_a16 : g_p16) + (size_t)row * DDIM);

    float s = 0.0f;
    float4 v0[4], v1[4];
    #pragma unroll
    for (int i = 0; i < 4; i++) {
        v0[i] = src[i * 64 + lane * 2];
        v1[i] = src[i * 64 + lane * 2 + 1];
        s += v0[i].x * v0[i].x + v0[i].y * v0[i].y + v0[i].z * v0[i].z + v0[i].w * v0[i].w;
        s += v1[i].x * v1[i].x + v1[i].y * v1[i].y + v1[i].z * v1[i].z + v1[i].w * v1[i].w;
    }
    #pragma unroll
    for (int i = 0; i < 4; i++) {
        uint4 pk;
        pk.x = h2_bits(__floats2half2_rn(v0[i].x, v0[i].y));
        pk.y = h2_bits(__floats2half2_rn(v0[i].z, v0[i].w));
        pk.z = h2_bits(__floats2half2_rn(v1[i].x, v1[i].y));
        pk.w = h2_bits(__floats2half2_rn(v1[i].z, v1[i].w));
        dst[i * 32 + lane] = pk;
    }
    #pragma unroll
    for (int o = 16; o > 0; o >>= 1) s += __shfl_xor_sync(0xffffffffu, s, o);
    if (lane == 0) {
        float inv = 1.0f / fmaxf(sqrtf(s), 1e-8f);
        if (isA) g_inv_a[row] = inv; else g_inv_p[row] = inv;
    }
}

// ---------------------------------------------------------------------------
// 2) fp16 mma.sync GEMM, 128x128 tile, XOR-swizzled smem, NS=3, 2 CTAs/SM.
//    grid=(32,32), block=256. R10 base; mainloop reordered to issue the
//    next-next chunk's loads BEFORE blocking on the current chunk.
// ---------------------------------------------------------------------------
__device__ __forceinline__ void load_chunk(char* smc, int c, int tid,
                                           const __half* Ab, const __half* Pb) {
    char* st = smc + (c % NS) * STAGE_B;
    const int k0 = c * KC;
    const int row = tid >> 3, q = tid & 7;
    #pragma unroll
    for (int j = 0; j < 4; j++) {
        int r = j * 32 + row;
        uint32_t dst = smem_u32(st + r * ROW_B + ((q ^ (r & 7)) << 4));
        cp_async16(dst, Ab + (size_t)r * DDIM + k0 + q * 8);
    }
    char* stb = st + TILE_B;
    #pragma unroll
    for (int j = 0; j < 4; j++) {
        int r = j * 32 + row;
        uint32_t dst = smem_u32(stb + r * ROW_B + ((q ^ (r & 7)) << 4));
        cp_async16(dst, Pb + (size_t)r * DDIM + k0 + q * 8);
    }
    CP_COMMIT();
}

__global__ __launch_bounds__(256, 2) void gemm_mma_kernel() {
    extern __shared__ char smc[];
    __shared__ float s_ia[TM];
    __shared__ float s_ip[TN];
    __shared__ float red[TM][2];

    const int tid  = threadIdx.x;
    const int lane = tid & 31;
    const int wid  = tid >> 5;
    const int wm   = (wid & 3) * 32;
    const int wn   = (wid >> 2) * 64;
    const int brow = blockIdx.y, bcol = blockIdx.x;

    const __half* Ab = g_a16 + (size_t)brow * TM * DDIM;
    const __half* Pb = g_p16 + (size_t)bcol * TN * DDIM;

    if (tid < 128)       s_ia[tid]       = SCALE * g_inv_a[brow * TM + tid];
    else                 s_ip[tid - 128] = g_inv_p[bcol * TN + (tid - 128)];

    #pragma unroll
    for (int c = 0; c < NS - 1; c++) load_chunk(smc, c, tid, Ab, Pb);

    float acc[2][8][4];
    #pragma unroll
    for (int mt = 0; mt < 2; mt++)
        #pragma unroll
        for (int nt = 0; nt < 8; nt++)
            #pragma unroll
            for (int r = 0; r < 4; r++) acc[mt][nt][r] = 0.0f;

    const int lt = lane >> 3, lr = lane & 7;
    int rowA[2], rowB[4];
    #pragma unroll
    for (int mt = 0; mt < 2; mt++) rowA[mt] = wm + mt * 16 + (lt & 1) * 8 + lr;
    #pragma unroll
    for (int np = 0; np < 4; np++) rowB[np] = wn + np * 16 + (lt >> 1) * 8 + lr;
    const int idxA = lt >> 1;
    const int idxB = lt & 1;

    for (int c = 0; c < NCHUNK; c++) {
        // barrier 1: all warps done reading stage (c+2)%NS (chunk c-1's LDSMs)
        __syncthreads();
        // issue chunk c+2 BEFORE blocking on chunk c (one commit per iteration;
        // empty commit at the tail keeps wait_group arithmetic uniform)
        if (c + NS - 1 < NCHUNK) load_chunk(smc, c + NS - 1, tid, Ab, Pb);
        else                     CP_COMMIT();
        // groups outstanding: {c, c+1, c+2} -> wait until <=2 => chunk c landed
        cp_wait<2>();
        // barrier 2: publish every thread's chunk-c data to all warps
        __syncthreads();

        const char* sA = smc + (c % NS) * STAGE_B;
        const char* sB = sA + TILE_B;

        #pragma unroll
        for (int kk = 0; kk < 4; kk++) {
            uint32_t a[2][4], bf[16];
            #pragma unroll
            for (int mt = 0; mt < 2; mt++) {
                int slot = (idxA | (kk << 1)) ^ (rowA[mt] & 7);
                ldsm_x4(a[mt], smem_u32(sA + rowA[mt] * ROW_B + (slot << 4)));
            }
            #pragma unroll
            for (int np = 0; np < 4; np++) {
                int slot = (idxB | (kk << 1)) ^ (rowB[np] & 7);
                ldsm_x4(&bf[np * 4], smem_u32(sB + rowB[np] * ROW_B + (slot << 4)));
            }
            #pragma unroll
            for (int mt = 0; mt < 2; mt++)
                #pragma unroll
                for (int nt = 0; nt < 8; nt++)
                    mma_f16(acc[mt][nt], a[mt], &bf[nt * 2]);
        }
    }
    __syncthreads();

    float rs[2][2] = {{0.0f, 0.0f}, {0.0f, 0.0f}};
    #pragma unroll
    for (int mt = 0; mt < 2; mt++) {
        #pragma unroll
        for (int h = 0; h < 2; h++) {
            const int rloc = wm + mt * 16 + (lane >> 2) + h * 8;
            const float ia = s_ia[rloc];
            const int grow = brow * TM + rloc;
            float acc_rs = 0.0f;
            #pragma unroll
            for (int nt = 0; nt < 8; nt++) {
                const int cbase = wn + nt * 8 + (lane & 3) * 2;
                const float ip0 = s_ip[cbase], ip1 = s_ip[cbase + 1];
                float s0 = acc[mt][nt][h * 2 + 0] * ia * ip0;
                float s1 = acc[mt][nt][h * 2 + 1] * ia * ip1;
                acc_rs += __expf(s0 - SCALE) + __expf(s1 - SCALE);
                if (brow == bcol) {
                    if (rloc == cbase)     g_diag[grow] = s0;
                    if (rloc == cbase + 1) g_diag[grow] = s1;
                }
            }
            rs[mt][h] = acc_rs;
        }
    }
    #pragma unroll
    for (int mt = 0; mt < 2; mt++)
        #pragma unroll
        for (int h = 0; h < 2; h++) {
            rs[mt][h] += __shfl_xor_sync(0xffffffffu, rs[mt][h], 1);
            rs[mt][h] += __shfl_xor_sync(0xffffffffu, rs[mt][h], 2);
        }
    if ((lane & 3) == 0) {
        #pragma unroll
        for (int mt = 0; mt < 2; mt++)
            #pragma unroll
            for (int h = 0; h < 2; h++)
                red[wm + mt * 16 + (lane >> 2) + h * 8][wid >> 2] = rs[mt][h];
    }
    __syncthreads();
    if (tid < TM) {
        float t = red[tid][0] + red[tid][1];
        g_partial[(size_t)(brow * TM + tid) * NBLK + bcol] = t;
    }
}

// ---------------------------------------------------------------------------
// 3) Fused tail: per-row loss, per-block sum, last block finalizes (fixed
//    order -> deterministic). g_count reset for graph replays.
// ---------------------------------------------------------------------------
__global__ void rowloss_kernel(float* __restrict__ out) {
    __shared__ float ws[4];
    const int r = blockIdx.x * 128 + threadIdx.x;
    float s = 0.0f;
    #pragma unroll
    for (int c = 0; c < NBLK; c++) s += g_partial[(size_t)r * NBLK + c];
    float rl = logf(s) + SCALE - g_diag[r];
    #pragma unroll
    for (int o = 16; o > 0; o >>= 1) rl += __shfl_xor_sync(0xffffffffu, rl, o);
    if ((threadIdx.x & 31) == 0) ws[threadIdx.x >> 5] = rl;
    __syncthreads();
    if (threadIdx.x == 0) {
        g_blocksum[blockIdx.x] = ws[0] + ws[1] + ws[2] + ws[3];
        __threadfence();
        int v = atomicAdd(&g_count, 1);
        if (v == NBLK - 1) {
            float t = 0.0f;
            #pragma unroll
            for (int i = 0; i < NBLK; i++) t += g_blocksum[i];
            out[0] = t * (1.0f / (float)BDIM);
            g_count = 0;
        }
    }
}

// ---------------------------------------------------------------------------
extern "C" void kernel_launch(void* const* d_in, const int* in_sizes, int n_in,
                              void* d_out, int out_size) {
    const float* A = (const float*)d_in[0];   // anchor_emb  [4096, 1024]
    const float* P = (const float*)d_in[1];   // pos_negs_emb[4096, 1024]
    float* out = (float*)d_out;

    const int smem = NS * STAGE_B;            // 98304 B -> 2 CTAs/SM
    cudaFuncSetAttribute(gemm_mma_kernel,
                         cudaFuncAttributeMaxDynamicSharedMemorySize, smem);

    norm_kernel<<<1024, 256>>>(A, P);
    gemm_mma_kernel<<<dim3(NBLK, NBLK), 256, smem>>>();
    rowloss_kernel<<<NBLK, 128>>>(out);
}

// round 14
// speedup vs baseline: 1.1706x; 1.1119x over previous
#include <cuda_runtime.h>
#include <cuda_fp16.h>
#include <cstdint>
#include <math.h>

#define BDIM 4096
#define DDIM 1024
#define TM 128
#define TN 128
#define NBLK (BDIM / TM)      // 32 row/col blocks
#define NS 3                  // cp.async pipeline stages
#define KC 64                 // k-halfs per chunk
#define NCHUNK (DDIM / KC)    // 16
#define ROW_B 128             // bytes per smem row (no padding; XOR swizzle)
#define TILE_B (TM * ROW_B)   // 16384 B per tile
#define STAGE_B (2 * TILE_B)  // A + B per stage = 32768 B
#define SCALE 20.0f

// Scratch (allocation-free per harness rules)
__device__ __half g_a16[BDIM * DDIM];
__device__ __half g_p16[BDIM * DDIM];
__device__ float g_inv_a[BDIM];
__device__ float g_inv_p[BDIM];
__device__ float g_partial[BDIM * NBLK];
__device__ float g_diag[BDIM];
__device__ float g_blocksum[NBLK];
__device__ int g_count;               // zero-init; reset to 0 after each use

// ---------------------------------------------------------------- helpers
__device__ __forceinline__ uint32_t smem_u32(const void* p) {
    uint32_t a;
    asm("{ .reg .u64 t; cvta.to.shared.u64 t, %1; cvt.u32.u64 %0, t; }" : "=r"(a) : "l"(p));
    return a;
}
__device__ __forceinline__ uint32_t h2_bits(__half2 h) {
    return *reinterpret_cast<const uint32_t*>(&h);
}
__device__ __forceinline__ void cp_async16(uint32_t dst, const void* src) {
    asm volatile("cp.async.cg.shared.global [%0], [%1], 16;" :: "r"(dst), "l"(src));
}
#define CP_COMMIT() asm volatile("cp.async.commit_group;" ::: "memory")
template <int N>
__device__ __forceinline__ void cp_wait() {
    asm volatile("cp.async.wait_group %0;" :: "n"(N) : "memory");
}
__device__ __forceinline__ void ldsm_x4(uint32_t* r, uint32_t addr) {
    asm volatile("ldmatrix.sync.aligned.m8n8.x4.shared.b16 {%0,%1,%2,%3}, [%4];"
                 : "=r"(r[0]), "=r"(r[1]), "=r"(r[2]), "=r"(r[3]) : "r"(addr));
}
// fp16 tensor-core MMA, fp32 accumulate: base-target PTX (sm_80+).
__device__ __forceinline__ void mma_f16(float* d, const uint32_t* a, const uint32_t* b) {
    asm volatile(
        "mma.sync.aligned.m16n8k16.row.col.f32.f16.f16.f32 "
        "{%0,%1,%2,%3}, {%4,%5,%6,%7}, {%8,%9}, {%0,%1,%2,%3};"
        : "+f"(d[0]), "+f"(d[1]), "+f"(d[2]), "+f"(d[3])
        : "r"(a[0]), "r"(a[1]), "r"(a[2]), "r"(a[3]), "r"(b[0]), "r"(b[1]));
}

// ---------------------------------------------------------------------------
// 1) Row inverse norms + fp32->fp16 conversion. One warp per row (R10 best).
// ---------------------------------------------------------------------------
__global__ void norm_kernel(const float* __restrict__ A, const float* __restrict__ P) {
    const int row  = (blockIdx.x & 511) * 8 + (threadIdx.x >> 5);
    const bool isA = blockIdx.x < 512;
    const int lane = threadIdx.x & 31;
    const float4* src = (const float4*)((isA ? A : P) + (size_t)row * DDIM);
    uint4* dst = (uint4*)((isA ? g_a16 : g_p16) + (size_t)row * DDIM);

    float s = 0.0f;
    float4 v0[4], v1[4];
    #pragma unroll
    for (int i = 0; i < 4; i++) {
        v0[i] = src[i * 64 + lane * 2];
        v1[i] = src[i * 64 + lane * 2 + 1];
        s += v0[i].x * v0[i].x + v0[i].y * v0[i].y + v0[i].z * v0[i].z + v0[i].w * v0[i].w;
        s += v1[i].x * v1[i].x + v1[i].y * v1[i].y + v1[i].z * v1[i].z + v1[i].w * v1[i].w;
    }
    #pragma unroll
    for (int i = 0; i < 4; i++) {
        uint4 pk;
        pk.x = h2_bits(__floats2half2_rn(v0[i].x, v0[i].y));
        pk.y = h2_bits(__floats2half2_rn(v0[i].z, v0[i].w));
        pk.z = h2_bits(__floats2half2_rn(v1[i].x, v1[i].y));
        pk.w = h2_bits(__floats2half2_rn(v1[i].z, v1[i].w));
        dst[i * 32 + lane] = pk;
    }
    #pragma unroll
    for (int o = 16; o > 0; o >>= 1) s += __shfl_xor_sync(0xffffffffu, s, o);
    if (lane == 0) {
        float inv = 1.0f / fmaxf(sqrtf(s), 1e-8f);
        if (isA) g_inv_a[row] = inv; else g_inv_p[row] = inv;
    }
}

// ---------------------------------------------------------------------------
// 2) fp16 mma.sync GEMM, 128x128 tile, 4 warps (64x64 warp tile), XOR-swizzle,
//    NS=3, 2 CTAs/SM. grid=(32,32), block=128.
// ---------------------------------------------------------------------------
__device__ __forceinline__ void load_chunk(char* smc, int c, int tid,
                                           const __half* Ab, const __half* Pb) {
    char* st = smc + (c % NS) * STAGE_B;
    const int k0 = c * KC;
    const int rowb = tid >> 3, q = tid & 7;   // 16 rows / pass, 8 passes
    #pragma unroll
    for (int j = 0; j < 8; j++) {
        int r = j * 16 + rowb;
        uint32_t dst = smem_u32(st + r * ROW_B + ((q ^ (r & 7)) << 4));
        cp_async16(dst, Ab + (size_t)r * DDIM + k0 + q * 8);
    }
    char* stb = st + TILE_B;
    #pragma unroll
    for (int j = 0; j < 8; j++) {
        int r = j * 16 + rowb;
        uint32_t dst = smem_u32(stb + r * ROW_B + ((q ^ (r & 7)) << 4));
        cp_async16(dst, Pb + (size_t)r * DDIM + k0 + q * 8);
    }
    CP_COMMIT();
}

__global__ __launch_bounds__(128, 2) void gemm_mma_kernel() {
    extern __shared__ char smc[];
    __shared__ float s_ia[TM];
    __shared__ float s_ip[TN];
    __shared__ float red[TM][2];

    const int tid  = threadIdx.x;
    const int lane = tid & 31;
    const int wid  = tid >> 5;           // 0..3
    const int wm   = (wid >> 1) * 64;    // warp row offset (2x2 warp grid)
    const int wn   = (wid & 1) * 64;     // warp col offset
    const int brow = blockIdx.y, bcol = blockIdx.x;

    const __half* Ab = g_a16 + (size_t)brow * TM * DDIM;
    const __half* Pb = g_p16 + (size_t)bcol * TN * DDIM;

    s_ia[tid] = SCALE * g_inv_a[brow * TM + tid];   // 128 threads cover TM
    s_ip[tid] = g_inv_p[bcol * TN + tid];           // and TN

    #pragma unroll
    for (int c = 0; c < NS - 1; c++) load_chunk(smc, c, tid, Ab, Pb);

    float acc[4][8][4];
    #pragma unroll
    for (int mt = 0; mt < 4; mt++)
        #pragma unroll
        for (int nt = 0; nt < 8; nt++)
            #pragma unroll
            for (int r = 0; r < 4; r++) acc[mt][nt][r] = 0.0f;

    const int lt = lane >> 3, lr = lane & 7;
    int rowA[4], rowB[4];
    #pragma unroll
    for (int mt = 0; mt < 4; mt++) rowA[mt] = wm + mt * 16 + (lt & 1) * 8 + lr;
    #pragma unroll
    for (int np = 0; np < 4; np++) rowB[np] = wn + np * 16 + (lt >> 1) * 8 + lr;
    const int idxA = lt >> 1;
    const int idxB = lt & 1;

    for (int c = 0; c < NCHUNK; c++) {
        if (c == NCHUNK - 1) cp_wait<0>(); else cp_wait<1>();
        __syncthreads();   // publish chunk c; closes WAR on stage (c+2)%NS
        if (c + NS - 1 < NCHUNK) load_chunk(smc, c + NS - 1, tid, Ab, Pb);

        const char* sA = smc + (c % NS) * STAGE_B;
        const char* sB = sA + TILE_B;

        #pragma unroll
        for (int kk = 0; kk < 4; kk++) {
            uint32_t a[4][4], bf[16];
            #pragma unroll
            for (int mt = 0; mt < 4; mt++) {
                int slot = (idxA | (kk << 1)) ^ (rowA[mt] & 7);
                ldsm_x4(a[mt], smem_u32(sA + rowA[mt] * ROW_B + (slot << 4)));
            }
            #pragma unroll
            for (int np = 0; np < 4; np++) {
                int slot = (idxB | (kk << 1)) ^ (rowB[np] & 7);
                ldsm_x4(&bf[np * 4], smem_u32(sB + rowB[np] * ROW_B + (slot << 4)));
            }
            #pragma unroll
            for (int mt = 0; mt < 4; mt++)
                #pragma unroll
                for (int nt = 0; nt < 8; nt++)
                    mma_f16(acc[mt][nt], a[mt], &bf[nt * 2]);
        }
    }
    __syncthreads();

    // Epilogue: s = acc * (20*inv_a) * inv_p ; per-row sum of exp(s-20); diag.
    float rs[4][2];
    #pragma unroll
    for (int mt = 0; mt < 4; mt++) {
        #pragma unroll
        for (int h = 0; h < 2; h++) {
            const int rloc = wm + mt * 16 + (lane >> 2) + h * 8;
            const float ia = s_ia[rloc];
            const int grow = brow * TM + rloc;
            float acc_rs = 0.0f;
            #pragma unroll
            for (int nt = 0; nt < 8; nt++) {
                const int cbase = wn + nt * 8 + (lane & 3) * 2;
                const float ip0 = s_ip[cbase], ip1 = s_ip[cbase + 1];
                float s0 = acc[mt][nt][h * 2 + 0] * ia * ip0;
                float s1 = acc[mt][nt][h * 2 + 1] * ia * ip1;
                acc_rs += __expf(s0 - SCALE) + __expf(s1 - SCALE);
                if (brow == bcol) {
                    if (rloc == cbase)     g_diag[grow] = s0;
                    if (rloc == cbase + 1) g_diag[grow] = s1;
                }
            }
            rs[mt][h] = acc_rs;
        }
    }
    #pragma unroll
    for (int mt = 0; mt < 4; mt++)
        #pragma unroll
        for (int h = 0; h < 2; h++) {
            rs[mt][h] += __shfl_xor_sync(0xffffffffu, rs[mt][h], 1);
            rs[mt][h] += __shfl_xor_sync(0xffffffffu, rs[mt][h], 2);
        }
    if ((lane & 3) == 0) {
        #pragma unroll
        for (int mt = 0; mt < 4; mt++)
            #pragma unroll
            for (int h = 0; h < 2; h++)
                red[wm + mt * 16 + (lane >> 2) + h * 8][wid & 1] = rs[mt][h];
    }
    __syncthreads();
    // 128 threads cover all TM rows; two column-half contributions per row.
    {
        float t = red[tid][0] + red[tid][1];
        g_partial[(size_t)(brow * TM + tid) * NBLK + bcol] = t;
    }
}

// ---------------------------------------------------------------------------
// 3) Fused tail: per-row loss, per-block sum, last block finalizes (fixed
//    order -> deterministic). g_count reset for graph replays.
// ---------------------------------------------------------------------------
__global__ void rowloss_kernel(float* __restrict__ out) {
    __shared__ float ws[4];
    const int r = blockIdx.x * 128 + threadIdx.x;
    float s = 0.0f;
    #pragma unroll
    for (int c = 0; c < NBLK; c++) s += g_partial[(size_t)r * NBLK + c];
    float rl = logf(s) + SCALE - g_diag[r];
    #pragma unroll
    for (int o = 16; o > 0; o >>= 1) rl += __shfl_xor_sync(0xffffffffu, rl, o);
    if ((threadIdx.x & 31) == 0) ws[threadIdx.x >> 5] = rl;
    __syncthreads();
    if (threadIdx.x == 0) {
        g_blocksum[blockIdx.x] = ws[0] + ws[1] + ws[2] + ws[3];
        __threadfence();
        int v = atomicAdd(&g_count, 1);
        if (v == NBLK - 1) {
            float t = 0.0f;
            #pragma unroll
            for (int i = 0; i < NBLK; i++) t += g_blocksum[i];
            out[0] = t * (1.0f / (float)BDIM);
            g_count = 0;
        }
    }
}

// ---------------------------------------------------------------------------
extern "C" void kernel_launch(void* const* d_in, const int* in_sizes, int n_in,
                              void* d_out, int out_size) {
    const float* A = (const float*)d_in[0];   // anchor_emb  [4096, 1024]
    const float* P = (const float*)d_in[1];   // pos_negs_emb[4096, 1024]
    float* out = (float*)d_out;

    const int smem = NS * STAGE_B;            // 98304 B -> 2 CTAs/SM
    cudaFuncSetAttribute(gemm_mma_kernel,
                         cudaFuncAttributeMaxDynamicSharedMemorySize, smem);

    norm_kernel<<<1024, 256>>>(A, P);
    gemm_mma_kernel<<<dim3(NBLK, NBLK), 128, smem>>>();
    rowloss_kernel<<<NBLK, 128>>>(out);
}